// round 1
// baseline (speedup 1.0000x reference)
#include <cuda_runtime.h>
#include <cuda_bf16.h>
#include <math.h>

// Problem constants
#define B_    16
#define CIN   16
#define DIN   32
#define HIN   32
#define WIN   32
#define COUT  32
#define KK    3
#define DO_   30
#define HO_   30
#define WO_   30

#define TPB   128   // threads per block
#define SPT   8     // spatial positions per thread (128*8 = 1024 >= 900)
#define CPT   8     // couts per block (4 cout groups in grid.z)

#define NSPAT (HO_ * WO_)   // 900 spatial positions per (b, d) slice

__global__ __launch_bounds__(TPB, 4)
void conv3d_fused_kernel(const float* __restrict__ x,
                         const float* __restrict__ w,
                         const float* __restrict__ conv_bias,
                         const float* __restrict__ scale,
                         const float* __restrict__ biasp,
                         float* __restrict__ out)
{
    __shared__ float sx[3 * HIN * WIN];          // 3 input depth slices: 3072 floats = 12 KB
    __shared__ float sw[CIN * 27 * CPT];         // 8 couts x 16 cin x 27 taps = 13.8 KB

    const int d0 = blockIdx.x;       // output depth slice (0..29)
    const int b  = blockIdx.y;       // batch
    const int cg = blockIdx.z;       // cout group: couts [cg*8, cg*8+8)
    const int t  = threadIdx.x;

    // ---- Stage weights for this cout group into smem.
    // Layout: sw[(cin*27 + k)*CPT + c]  -> broadcast-friendly (same addr all lanes)
    for (int i = t; i < CIN * 27 * CPT; i += TPB) {
        int c    = i & (CPT - 1);
        int rest = i >> 3;              // cin*27 + k
        int cin  = rest / 27;
        int k    = rest - cin * 27;
        sw[i] = w[(((cg * CPT + c) * CIN + cin) * 27) + k];
    }

    // ---- Precompute this thread's spatial coordinates (clamped; mask at store).
    int hh[SPT], ww[SPT];
    bool live[SPT];
    #pragma unroll
    for (int s = 0; s < SPT; ++s) {
        int pos = s * TPB + t;
        live[s] = (pos < NSPAT);
        int p = live[s] ? pos : (NSPAT - 1);   // clamp keeps smem reads in bounds
        hh[s] = p / WO_;
        ww[s] = p - hh[s] * WO_;
    }

    float acc[SPT][CPT];
    #pragma unroll
    for (int s = 0; s < SPT; ++s)
        #pragma unroll
        for (int c = 0; c < CPT; ++c)
            acc[s][c] = 0.0f;

    const float* xb = x + ((long)b * CIN) * (DIN * HIN * WIN) + d0 * (HIN * WIN);

    // ---- Main loop over input channels: stage 3-slice slab, accumulate.
    for (int cin = 0; cin < CIN; ++cin) {
        __syncthreads();   // protect previous slab until all consumers done
        const float4* xp4 = reinterpret_cast<const float4*>(xb + cin * (DIN * HIN * WIN));
        float4* sx4 = reinterpret_cast<float4*>(sx);
        #pragma unroll
        for (int i = t; i < (3 * HIN * WIN) / 4; i += TPB)
            sx4[i] = xp4[i];
        __syncthreads();

        #pragma unroll
        for (int kd = 0; kd < KK; ++kd) {
            #pragma unroll
            for (int kh = 0; kh < KK; ++kh) {
                #pragma unroll
                for (int kw = 0; kw < KK; ++kw) {
                    const int kidx = (kd * 3 + kh) * 3 + kw;
                    float wr[CPT];
                    #pragma unroll
                    for (int c = 0; c < CPT; ++c)
                        wr[c] = sw[(cin * 27 + kidx) * CPT + c];   // broadcast LDS
                    #pragma unroll
                    for (int s = 0; s < SPT; ++s) {
                        float xv = sx[kd * (HIN * WIN) + (hh[s] + kh) * WIN + (ww[s] + kw)];
                        #pragma unroll
                        for (int c = 0; c < CPT; ++c)
                            acc[s][c] = fmaf(xv, wr[c], acc[s][c]);
                    }
                }
            }
        }
    }

    // ---- Epilogue: bias, scale, tanh, bias_param, sigmoid; coalesced store.
    #pragma unroll
    for (int c = 0; c < CPT; ++c) {
        const int co = cg * CPT + c;
        const float cbv = conv_bias[co];
        const float sfv = scale[co];
        const float bpv = biasp[co];
        float* ob = out + ((((long)b * COUT + co) * DO_ + d0) * HO_) * WO_;
        #pragma unroll
        for (int s = 0; s < SPT; ++s) {
            if (live[s]) {
                float y = (acc[s][c] + cbv) * sfv;
                y = tanhf(y) * bpv;
                y = 1.0f / (1.0f + expf(-y));
                ob[hh[s] * WO_ + ww[s]] = y;
            }
        }
    }
}

extern "C" void kernel_launch(void* const* d_in, const int* in_sizes, int n_in,
                              void* d_out, int out_size)
{
    const float* x    = (const float*)d_in[0];
    const float* w    = (const float*)d_in[1];
    const float* cb   = (const float*)d_in[2];
    const float* sf   = (const float*)d_in[3];
    const float* bp   = (const float*)d_in[4];
    float* out        = (float*)d_out;

    dim3 grid(DO_, B_, COUT / CPT);   // 30 x 16 x 4 = 1920 blocks
    conv3d_fused_kernel<<<grid, TPB>>>(x, w, cb, sf, bp, out);
}

// round 2
// speedup vs baseline: 1.0491x; 1.0491x over previous
#include <cuda_runtime.h>
#include <math.h>

// Problem constants
#define B_    16
#define CIN   16
#define DIN   32
#define HIN   32
#define WIN   32
#define COUT  32
#define DO_   30
#define HO_   30
#define WO_   30

#define TPB   128
#define CPT   8          // couts per block (grid.z = 4)
#define NCH   240        // 30 rows * 8 four-wide w-chunks per (b,d0) slice
#define SLAB  (3 * HIN * WIN)   // 3072 floats per cin slab

__device__ __forceinline__ void cp_async16(void* sdst, const void* gsrc) {
    unsigned s = (unsigned)__cvta_generic_to_shared(sdst);
    asm volatile("cp.async.cg.shared.global [%0], [%1], 16;\n" :: "r"(s), "l"(gsrc));
}
__device__ __forceinline__ void cp_commit() {
    asm volatile("cp.async.commit_group;\n" ::: "memory");
}
__device__ __forceinline__ void cp_wait1() {
    asm volatile("cp.async.wait_group 1;\n" ::: "memory");
}

__global__ __launch_bounds__(TPB, 4)
void conv3d_fused_kernel(const float* __restrict__ x,
                         const float* __restrict__ w,
                         const float* __restrict__ conv_bias,
                         const float* __restrict__ scale,
                         const float* __restrict__ biasp,
                         float* __restrict__ out)
{
    // +16 pad: w0=28 chunks vector-read 4 floats past a row end; those values
    // feed only store-masked accumulators, pad keeps the read in-bounds.
    __shared__ float sx[2][SLAB + 16];
    __shared__ float sw[CIN * 27 * CPT];     // [cin][kidx][c], c fastest -> LDS.128

    const int d0 = blockIdx.x;
    const int b  = blockIdx.y;
    const int cg = blockIdx.z;
    const int t  = threadIdx.x;

    // ---- Stage weights (once per block).
    for (int i = t; i < CIN * 27 * CPT; i += TPB) {
        int c    = i & (CPT - 1);
        int rest = i >> 3;
        int cin  = rest / 27;
        int k    = rest - cin * 27;
        sw[i] = w[(((cg * CPT + c) * CIN + cin) * 27) + k];
    }

    // ---- Chunk setup: thread owns chunks t and t+128; chunk = 4 consecutive w.
    int hh[2], w0[2];
    bool valid[2];
    #pragma unroll
    for (int ch = 0; ch < 2; ++ch) {
        int id = t + ch * TPB;
        valid[ch] = (id < NCH);
        int idc = valid[ch] ? id : 0;     // clamp: dead chunks compute row 0 (discarded)
        hh[ch] = idc >> 3;
        w0[ch] = (idc & 7) * 4;
    }
    const int soff0 = hh[0] * WIN + w0[0];
    const int soff1 = hh[1] * WIN + w0[1];

    float acc[2][4][CPT];
    #pragma unroll
    for (int ch = 0; ch < 2; ++ch)
        #pragma unroll
        for (int i = 0; i < 4; ++i)
            #pragma unroll
            for (int c = 0; c < CPT; ++c)
                acc[ch][i][c] = 0.0f;

    const float* xbase = x + ((long)b * CIN) * (DIN * HIN * WIN) + d0 * (HIN * WIN);

    // ---- Prefetch slabs for cin 0 and 1.
    {
        const float4* g0 = (const float4*)(xbase);
        const float4* g1 = (const float4*)(xbase + (DIN * HIN * WIN));
        float4* s0 = (float4*)sx[0];
        float4* s1 = (float4*)sx[1];
        #pragma unroll
        for (int i = 0; i < 6; ++i) cp_async16(&s0[t + i * TPB], &g0[t + i * TPB]);
        cp_commit();
        #pragma unroll
        for (int i = 0; i < 6; ++i) cp_async16(&s1[t + i * TPB], &g1[t + i * TPB]);
        cp_commit();
    }

    // ---- Main loop over input channels.
    for (int cin = 0; cin < CIN; ++cin) {
        cp_wait1();          // current buffer's group complete
        __syncthreads();     // also covers sw staging on first iteration

        const float* sb  = sx[cin & 1];
        const float* swc = &sw[cin * 27 * CPT];

        #pragma unroll
        for (int kd = 0; kd < 3; ++kd) {
            #pragma unroll
            for (int kh = 0; kh < 3; ++kh) {
                const int rb0 = kd * (HIN * WIN) + kh * WIN + soff0;
                const int rb1 = kd * (HIN * WIN) + kh * WIN + soff1;
                float4 a0 = *(const float4*)&sb[rb0];
                float4 b0 = *(const float4*)&sb[rb0 + 4];
                float4 a1 = *(const float4*)&sb[rb1];
                float4 b1 = *(const float4*)&sb[rb1 + 4];
                float x0[8] = {a0.x, a0.y, a0.z, a0.w, b0.x, b0.y, b0.z, b0.w};
                float x1[8] = {a1.x, a1.y, a1.z, a1.w, b1.x, b1.y, b1.z, b1.w};

                #pragma unroll
                for (int kw = 0; kw < 3; ++kw) {
                    const float* wp = &swc[((kd * 3 + kh) * 3 + kw) * CPT];
                    float4 wlo = *(const float4*)wp;
                    float4 whi = *(const float4*)(wp + 4);
                    float wv[8] = {wlo.x, wlo.y, wlo.z, wlo.w,
                                   whi.x, whi.y, whi.z, whi.w};
                    #pragma unroll
                    for (int i = 0; i < 4; ++i) {
                        const float xv0 = x0[i + kw];
                        const float xv1 = x1[i + kw];
                        #pragma unroll
                        for (int c = 0; c < CPT; ++c) {
                            acc[0][i][c] = fmaf(xv0, wv[c], acc[0][i][c]);
                            acc[1][i][c] = fmaf(xv1, wv[c], acc[1][i][c]);
                        }
                    }
                }
            }
        }

        __syncthreads();     // all reads of buf[cin&1] done before overwrite
        if (cin + 2 < CIN) {
            const float4* g = (const float4*)(xbase + (long)(cin + 2) * (DIN * HIN * WIN));
            float4* s = (float4*)sx[cin & 1];
            #pragma unroll
            for (int i = 0; i < 6; ++i) cp_async16(&s[t + i * TPB], &g[t + i * TPB]);
        }
        cp_commit();         // commit (possibly empty) to keep group accounting aligned
    }

    // ---- Epilogue: bias, scale, tanh, bias_param, sigmoid.
    #pragma unroll
    for (int c = 0; c < CPT; ++c) {
        const int co = cg * CPT + c;
        const float cbv = conv_bias[co];
        const float sfv = scale[co];
        const float bpv = biasp[co];
        float* ob = out + (((long)b * COUT + co) * DO_ + d0) * (HO_ * WO_);
        #pragma unroll
        for (int ch = 0; ch < 2; ++ch) {
            if (!valid[ch]) continue;
            #pragma unroll
            for (int i = 0; i < 4; ++i) {
                const int wq = w0[ch] + i;
                if (wq < WO_) {
                    float y = (acc[ch][i][c] + cbv) * sfv;
                    y = tanhf(y) * bpv;
                    ob[hh[ch] * WO_ + wq] = 1.0f / (1.0f + expf(-y));
                }
            }
        }
    }
}

extern "C" void kernel_launch(void* const* d_in, const int* in_sizes, int n_in,
                              void* d_out, int out_size)
{
    const float* x  = (const float*)d_in[0];
    const float* w  = (const float*)d_in[1];
    const float* cb = (const float*)d_in[2];
    const float* sf = (const float*)d_in[3];
    const float* bp = (const float*)d_in[4];
    float* out      = (float*)d_out;

    dim3 grid(DO_, B_, COUT / CPT);   // 30 x 16 x 4 = 1920 blocks
    conv3d_fused_kernel<<<grid, TPB>>>(x, w, cb, sf, bp, out);
}

// round 4
// speedup vs baseline: 1.8421x; 1.7560x over previous
#include <cuda_runtime.h>
#include <cuda_bf16.h>
#include <cstdint>
#include <math.h>

// ---------------- problem constants ----------------
#define DO_   30
#define TPB   256

// ---------------- device scratch (no runtime alloc) ----------------
// x transformed to [b][d][h][w][cin] bf16, hi/lo split
__device__ __align__(16) __nv_bfloat16 g_xt_hi[16 * 32 * 32 * 32 * 16];
__device__ __align__(16) __nv_bfloat16 g_xt_lo[16 * 32 * 32 * 32 * 16];
// weights [tap 27][prec 2][cout 32][cin 16] bf16
__device__ __align__(16) __nv_bfloat16 g_w2[27 * 2 * 32 * 16];

// ---------------- helpers ----------------
__device__ __forceinline__ uint32_t smem_u32(const void* p) {
    uint32_t a;
    asm("{ .reg .u64 t; cvta.to.shared.u64 t, %1; cvt.u32.u64 %0, t; }" : "=r"(a) : "l"(p));
    return a;
}
__device__ __forceinline__ void cp_async16(uint32_t sdst, const void* gsrc) {
    asm volatile("cp.async.cg.shared.global [%0], [%1], 16;\n" :: "r"(sdst), "l"(gsrc));
}
__device__ __forceinline__ void cp_commit() { asm volatile("cp.async.commit_group;\n" ::: "memory"); }
template<int N> __device__ __forceinline__ void cp_wait() {
    asm volatile("cp.async.wait_group %0;\n" :: "n"(N) : "memory");
}
__device__ __forceinline__ void ldsm4(uint32_t* r, uint32_t addr) {
    asm volatile("ldmatrix.sync.aligned.m8n8.x4.shared.b16 {%0,%1,%2,%3}, [%4];"
        : "=r"(r[0]), "=r"(r[1]), "=r"(r[2]), "=r"(r[3]) : "r"(addr));
}
__device__ __forceinline__ void mma_bf16(float* c, const uint32_t* a, const uint32_t* b) {
    asm volatile(
        "mma.sync.aligned.m16n8k16.row.col.f32.bf16.bf16.f32 "
        "{%0,%1,%2,%3}, {%4,%5,%6,%7}, {%8,%9}, {%0,%1,%2,%3};"
        : "+f"(c[0]), "+f"(c[1]), "+f"(c[2]), "+f"(c[3])
        : "r"(a[0]), "r"(a[1]), "r"(a[2]), "r"(a[3]), "r"(b[0]), "r"(b[1]));
}

// ---------------- transform kernels ----------------
// x: NCDHW fp32 -> g_xt_{hi,lo}[b][d][h][w][cin] bf16
__global__ __launch_bounds__(128) void xform_x(const float* __restrict__ x)
{
    __shared__ float s[16][33];
    const int blk = blockIdx.x;            // (b*32 + d)*32 + h
    const int b = blk >> 10, d = (blk >> 5) & 31, h = blk & 31;
    const int t = threadIdx.x;

    const int cin = t >> 3, w4 = (t & 7) << 2;
    const float4 v = *(const float4*)(x + (((long)(b * 16 + cin) << 15) + (d << 10) + (h << 5) + w4));
    s[cin][w4 + 0] = v.x; s[cin][w4 + 1] = v.y; s[cin][w4 + 2] = v.z; s[cin][w4 + 3] = v.w;
    __syncthreads();

    const long ob = (long)blk * 512;
    #pragma unroll
    for (int j = 0; j < 4; ++j) {
        const int e = t + (j << 7);        // = w*16 + cin
        const int w = e >> 4, c = e & 15;
        const float f = s[c][w];
        __nv_bfloat16 hi = __float2bfloat16(f);
        __nv_bfloat16 lo = __float2bfloat16(f - __bfloat162float(hi));
        g_xt_hi[ob + e] = hi;
        g_xt_lo[ob + e] = lo;
    }
}

// weights OIDHW fp32 -> [tap][prec][cout][cin] bf16
__global__ __launch_bounds__(128) void xform_w(const float* __restrict__ w)
{
    const int idx = blockIdx.x * 128 + threadIdx.x;
    if (idx >= 27 * 512) return;
    const int tap = idx >> 9, r = idx & 511;
    const int co = r >> 4, cin = r & 15;
    const float v = w[(co * 16 + cin) * 27 + tap];
    __nv_bfloat16 hi = __float2bfloat16(v);
    __nv_bfloat16 lo = __float2bfloat16(v - __bfloat162float(hi));
    g_w2[(tap * 2 + 0) * 512 + r] = hi;
    g_w2[(tap * 2 + 1) * 512 + r] = lo;
}

// ---------------- main kernel ----------------
// dynamic smem layout (bytes):
//   [0, 55296)         weights  [tap][prec][32 rows x 16 cin] (1024B per (tap,prec))
//   [55296, 110656)    slab_hi  3 slices x 576 rows x 32B + 2 pad rows (55360B)
//   [110656, 166016)   slab_lo
// epilogue overlays floats at offset 0 (512 x 34 pitch = 69632B)
#define SMEM_DYN 166016

__global__ __launch_bounds__(TPB, 1) void conv_main(
    const float* __restrict__ cbias,
    const float* __restrict__ sfac,
    const float* __restrict__ bparm,
    float* __restrict__ out)
{
    extern __shared__ char sm[];
    __shared__ float e0[32], e1[32], e2s[32];

    const int d0 = blockIdx.x, b = blockIdx.y, hh = blockIdx.z;
    const int t = threadIdx.x, warp = t >> 5, lane = t & 31;
    const uint32_t smb  = smem_u32(sm);
    const uint32_t ws_a = smb;
    const uint32_t sh_a = smb + 55296u;
    const uint32_t sl_a = smb + 110656u;

    const int hstart = hh * 16;
    const int rows_ld = hh ? 512 : 576;    // h rows available: 18 (halo) or 16 (top clip)
    const int chunks = rows_ld * 2;        // 16B chunks per slice per precision

    // ---- async loads: group0 = weights + d-slice0; group1 = slice1; group2 = slice2
    for (int i = t; i < 3456; i += TPB)
        cp_async16(ws_a + i * 16, (const char*)g_w2 + (long)i * 16);
    #pragma unroll
    for (int d = 0; d < 3; ++d) {
        const long bo = (long)(((b * 32 + d0 + d) * 32 + hstart)) * 1024;
        const char* ghp = (const char*)g_xt_hi + bo;
        const char* glp = (const char*)g_xt_lo + bo;
        const uint32_t dsth = sh_a + (uint32_t)d * 18432u;
        const uint32_t dstl = sl_a + (uint32_t)d * 18432u;
        for (int i = t; i < chunks; i += TPB) {
            cp_async16(dsth + i * 16, ghp + (long)i * 16);
            cp_async16(dstl + i * 16, glp + (long)i * 16);
        }
        cp_commit();
    }

    if (t < 32) {
        const float s = sfac[t];
        e0[t] = cbias[t] * s;
        e1[t] = s;
        e2s[t] = bparm[t];
    }

    float acc[4][4][4];
    #pragma unroll
    for (int rt = 0; rt < 4; ++rt)
        #pragma unroll
        for (int j = 0; j < 4; ++j)
            #pragma unroll
            for (int k = 0; k < 4; ++k)
                acc[rt][j][k] = 0.0f;

    // ldmatrix lane address components
    const uint32_t bn = (lane & 7) + ((lane & 16) >> 1);   // B: n row 0..15
    const uint32_t bc = (lane & 8) * 2;                    // B: k-half byte 0/16
    const uint32_t ar = (lane & 15);                       // A: row within tile
    const uint32_t ac = (lane & 16);                       // A: k-half byte 0/16

    #pragma unroll
    for (int kd = 0; kd < 3; ++kd) {
        if (kd == 0) cp_wait<2>(); else if (kd == 1) cp_wait<1>(); else cp_wait<0>();
        __syncthreads();

        #pragma unroll
        for (int kh = 0; kh < 3; ++kh) {
            #pragma unroll
            for (int kw = 0; kw < 3; ++kw) {
                const int tap = (kd * 3 + kh) * 3 + kw;
                const uint32_t roff = (uint32_t)(kd * 576 + kh * 32 + kw);

                // ---- B fragments (hi, lo) for all 4 n8 coltiles
                uint32_t bh[4][2], bl[4][2];
                {
                    const uint32_t base = ws_a + (uint32_t)(tap * 2) * 1024u + bn * 32u + bc;
                    uint32_t r0[4], r1[4];
                    ldsm4(r0, base);            // hi: n0-15
                    ldsm4(r1, base + 512u);     // hi: n16-31
                    bh[0][0] = r0[0]; bh[0][1] = r0[1]; bh[1][0] = r0[2]; bh[1][1] = r0[3];
                    bh[2][0] = r1[0]; bh[2][1] = r1[1]; bh[3][0] = r1[2]; bh[3][1] = r1[3];
                    ldsm4(r0, base + 1024u);    // lo: n0-15
                    ldsm4(r1, base + 1536u);    // lo: n16-31
                    bl[0][0] = r0[0]; bl[0][1] = r0[1]; bl[1][0] = r0[2]; bl[1][1] = r0[3];
                    bl[2][0] = r1[0]; bl[2][1] = r1[1]; bl[3][0] = r1[2]; bl[3][1] = r1[3];
                }

                const uint32_t arow0 = (uint32_t)(warp * 64) + roff + ar;
                #pragma unroll
                for (int rt = 0; rt < 4; ++rt) {
                    uint32_t ah[4], al[4];
                    const uint32_t aoff = (arow0 + (uint32_t)rt * 16u) * 32u + ac;
                    ldsm4(ah, sh_a + aoff);
                    ldsm4(al, sl_a + aoff);
                    #pragma unroll
                    for (int j = 0; j < 4; ++j) {
                        mma_bf16(acc[rt][j], ah, bh[j]);   // hi*hi
                        mma_bf16(acc[rt][j], ah, bl[j]);   // hi*lo
                        mma_bf16(acc[rt][j], al, bh[j]);   // lo*hi
                    }
                }
            }
        }
    }

    // ---- epilogue: stage raw accumulators to smem (transpose), then coalesced store
    __syncthreads();
    float* ep = (float*)sm;                      // [512][34] pitch
    const int g  = lane >> 2;
    const int cq = 2 * (lane & 3);
    #pragma unroll
    for (int rt = 0; rt < 4; ++rt) {
        const int R = warp * 64 + rt * 16 + g;
        #pragma unroll
        for (int j = 0; j < 4; ++j) {
            const int col = j * 8 + cq;
            *(float2*)&ep[R * 34 + col]       = make_float2(acc[rt][j][0], acc[rt][j][1]);
            *(float2*)&ep[(R + 8) * 34 + col] = make_float2(acc[rt][j][2], acc[rt][j][3]);
        }
    }
    __syncthreads();

    #pragma unroll 4
    for (int i = 0; i < 64; ++i) {
        const int co = i >> 1;
        const int r  = ((i & 1) << 8) + t;       // 0..511
        const int h  = hstart + (r >> 5);
        const int w  = r & 31;
        if (w < 30 && h < 30) {
            const float v = ep[r * 34 + co];
            float y = fmaf(v, e1[co], e0[co]);
            y = tanhf(y) * e2s[co];
            out[((((long)b * 32 + co) * DO_ + d0) * 30 + h) * 30 + w] =
                1.0f / (1.0f + __expf(-y));
        }
    }
}

// ---------------- launch ----------------
extern "C" void kernel_launch(void* const* d_in, const int* in_sizes, int n_in,
                              void* d_out, int out_size)
{
    const float* x  = (const float*)d_in[0];
    const float* w  = (const float*)d_in[1];
    const float* cb = (const float*)d_in[2];
    const float* sf = (const float*)d_in[3];
    const float* bp = (const float*)d_in[4];
    float* out      = (float*)d_out;

    cudaFuncSetAttribute(conv_main, cudaFuncAttributeMaxDynamicSharedMemorySize, SMEM_DYN);

    xform_x<<<16 * 32 * 32, 128>>>(x);
    xform_w<<<(27 * 512 + 127) / 128, 128>>>(w);

    dim3 grid(DO_, 16, 2);
    conv_main<<<grid, TPB, SMEM_DYN>>>(cb, sf, bp, out);
}

// round 5
// speedup vs baseline: 2.3086x; 1.2532x over previous
#include <cuda_runtime.h>
#include <cuda_bf16.h>
#include <cstdint>
#include <math.h>

#define DO_   30
#define TPB   256

// ---------------- device scratch (no runtime alloc) ----------------
__device__ __align__(16) __nv_bfloat16 g_xt_hi[16 * 32 * 32 * 32 * 16];
__device__ __align__(16) __nv_bfloat16 g_xt_lo[16 * 32 * 32 * 32 * 16];
// weights [tap 27][prec 2][cout 32][cin 16] bf16
__device__ __align__(16) __nv_bfloat16 g_w2[27 * 2 * 32 * 16];

// ---------------- helpers ----------------
__device__ __forceinline__ uint32_t smem_u32(const void* p) {
    uint32_t a;
    asm("{ .reg .u64 t; cvta.to.shared.u64 t, %1; cvt.u32.u64 %0, t; }" : "=r"(a) : "l"(p));
    return a;
}
__device__ __forceinline__ void cp_async16(uint32_t sdst, const void* gsrc) {
    asm volatile("cp.async.cg.shared.global [%0], [%1], 16;\n" :: "r"(sdst), "l"(gsrc));
}
__device__ __forceinline__ void cp_commit() { asm volatile("cp.async.commit_group;\n" ::: "memory"); }
template<int N> __device__ __forceinline__ void cp_wait() {
    asm volatile("cp.async.wait_group %0;\n" :: "n"(N) : "memory");
}
__device__ __forceinline__ void ldsm4(uint32_t* r, uint32_t addr) {
    asm volatile("ldmatrix.sync.aligned.m8n8.x4.shared.b16 {%0,%1,%2,%3}, [%4];"
        : "=r"(r[0]), "=r"(r[1]), "=r"(r[2]), "=r"(r[3]) : "r"(addr));
}
__device__ __forceinline__ void mma_bf16(float* c, const uint32_t* a, const uint32_t* b) {
    asm volatile(
        "mma.sync.aligned.m16n8k16.row.col.f32.bf16.bf16.f32 "
        "{%0,%1,%2,%3}, {%4,%5,%6,%7}, {%8,%9}, {%0,%1,%2,%3};"
        : "+f"(c[0]), "+f"(c[1]), "+f"(c[2]), "+f"(c[3])
        : "r"(a[0]), "r"(a[1]), "r"(a[2]), "r"(a[3]), "r"(b[0]), "r"(b[1]));
}

// ---------------- transform kernels (unchanged from R4) ----------------
__global__ __launch_bounds__(128) void xform_x(const float* __restrict__ x)
{
    __shared__ float s[16][33];
    const int blk = blockIdx.x;            // (b*32 + d)*32 + h
    const int b = blk >> 10, d = (blk >> 5) & 31, h = blk & 31;
    const int t = threadIdx.x;

    const int cin = t >> 3, w4 = (t & 7) << 2;
    const float4 v = *(const float4*)(x + (((long)(b * 16 + cin) << 15) + (d << 10) + (h << 5) + w4));
    s[cin][w4 + 0] = v.x; s[cin][w4 + 1] = v.y; s[cin][w4 + 2] = v.z; s[cin][w4 + 3] = v.w;
    __syncthreads();

    const long ob = (long)blk * 512;
    #pragma unroll
    for (int j = 0; j < 4; ++j) {
        const int e = t + (j << 7);        // = w*16 + cin
        const int w = e >> 4, c = e & 15;
        const float f = s[c][w];
        __nv_bfloat16 hi = __float2bfloat16(f);
        __nv_bfloat16 lo = __float2bfloat16(f - __bfloat162float(hi));
        g_xt_hi[ob + e] = hi;
        g_xt_lo[ob + e] = lo;
    }
}

__global__ __launch_bounds__(128) void xform_w(const float* __restrict__ w)
{
    const int idx = blockIdx.x * 128 + threadIdx.x;
    if (idx >= 27 * 512) return;
    const int tap = idx >> 9, r = idx & 511;
    const int co = r >> 4, cin = r & 15;
    const float v = w[(co * 16 + cin) * 27 + tap];
    __nv_bfloat16 hi = __float2bfloat16(v);
    __nv_bfloat16 lo = __float2bfloat16(v - __bfloat162float(hi));
    g_w2[(tap * 2 + 0) * 512 + r] = hi;
    g_w2[(tap * 2 + 1) * 512 + r] = lo;
}

// ---------------- main kernel ----------------
// dynamic smem (bytes):
//   [0, 55296)          weights [tap][prec][32 x 16cin]  (1024B per (tap,prec))
//   [55296, 96512)      slab: 4 buffers of 10304B = [buf(2)][prec(2)][322 rows x 32B]
// epilogue overlays floats at offset 0: 256 x 33 pitch = 33792B
#define SMEM_DYN 96512
#define SLAB0    55296
#define BUFSZ    10304

__global__ __launch_bounds__(TPB, 2) void conv_main(
    const float* __restrict__ cbias,
    const float* __restrict__ sfac,
    const float* __restrict__ bparm,
    float* __restrict__ out)
{
    extern __shared__ char sm[];
    __shared__ float e0[32], e1[32], e2s[32];

    const int d0 = blockIdx.x, b = blockIdx.y, hh = blockIdx.z;
    const int t = threadIdx.x, warp = t >> 5, lane = t & 31;
    const uint32_t smb = smem_u32(sm);
    const uint32_t ws_a = smb;

    const int hstart = hh * 8;
    const int rows_h = (hh == 3) ? 8 : 10;   // input h-rows available (halo; clipped at bottom)
    const int chunks = rows_h * 64;          // 16B chunks per precision per slice

    // ---- async loads: G0 = weights + slice kd0 (buf0); G1 = slice kd1 (buf1)
    for (int i = t; i < 3456; i += TPB)
        cp_async16(ws_a + i * 16, (const char*)g_w2 + (long)i * 16);
    #pragma unroll
    for (int buf = 0; buf < 2; ++buf) {
        const long bo = (long)((b * 32 + d0 + buf) * 32 + hstart) * 1024;
        const uint32_t dh = smb + SLAB0 + (uint32_t)(buf * 2) * BUFSZ;
        const uint32_t dl = dh + BUFSZ;
        for (int i = t; i < chunks; i += TPB) {
            cp_async16(dh + i * 16, (const char*)g_xt_hi + bo + (long)i * 16);
            cp_async16(dl + i * 16, (const char*)g_xt_lo + bo + (long)i * 16);
        }
        cp_commit();
    }

    if (t < 32) {
        const float s = sfac[t];
        e0[t] = cbias[t] * s;
        e1[t] = s;
        e2s[t] = bparm[t];
    }

    float acc[2][4][4];
    #pragma unroll
    for (int rt = 0; rt < 2; ++rt)
        #pragma unroll
        for (int j = 0; j < 4; ++j)
            #pragma unroll
            for (int k = 0; k < 4; ++k)
                acc[rt][j][k] = 0.0f;

    const uint32_t bn = (lane & 7) + ((lane & 16) >> 1);
    const uint32_t bc = (lane & 8) * 2;
    const uint32_t ar = (lane & 15);
    const uint32_t ac = (lane & 16);

    #pragma unroll
    for (int kd = 0; kd < 3; ++kd) {
        if (kd < 2) cp_wait<1>(); else cp_wait<0>();
        __syncthreads();

        const uint32_t sh_a = smb + SLAB0 + (uint32_t)((kd & 1) * 2) * BUFSZ;
        const uint32_t sl_a = sh_a + BUFSZ;

        #pragma unroll
        for (int kh = 0; kh < 3; ++kh) {
            #pragma unroll
            for (int kw = 0; kw < 3; ++kw) {
                const int tap = (kd * 3 + kh) * 3 + kw;
                const uint32_t roff = (uint32_t)(kh * 32 + kw);

                // B fragments (hi, lo), 4 n8 coltiles each
                uint32_t bh[4][2], bl[4][2];
                {
                    const uint32_t base = ws_a + (uint32_t)(tap * 2) * 1024u + bn * 32u + bc;
                    uint32_t r0[4], r1[4];
                    ldsm4(r0, base);
                    ldsm4(r1, base + 512u);
                    bh[0][0] = r0[0]; bh[0][1] = r0[1]; bh[1][0] = r0[2]; bh[1][1] = r0[3];
                    bh[2][0] = r1[0]; bh[2][1] = r1[1]; bh[3][0] = r1[2]; bh[3][1] = r1[3];
                    ldsm4(r0, base + 1024u);
                    ldsm4(r1, base + 1536u);
                    bl[0][0] = r0[0]; bl[0][1] = r0[1]; bl[1][0] = r0[2]; bl[1][1] = r0[3];
                    bl[2][0] = r1[0]; bl[2][1] = r1[1]; bl[3][0] = r1[2]; bl[3][1] = r1[3];
                }

                // A fragments for both rowtiles first (hide LDSM latency)
                uint32_t ah[2][4], al[2][4];
                const uint32_t arow0 = (uint32_t)(warp * 32) + roff + ar;
                #pragma unroll
                for (int rt = 0; rt < 2; ++rt) {
                    const uint32_t aoff = (arow0 + (uint32_t)rt * 16u) * 32u + ac;
                    ldsm4(ah[rt], sh_a + aoff);
                    ldsm4(al[rt], sl_a + aoff);
                }

                // Three passes, j-inner: consecutive MMAs into an acc are 4 apart
                #pragma unroll
                for (int rt = 0; rt < 2; ++rt)
                    #pragma unroll
                    for (int j = 0; j < 4; ++j)
                        mma_bf16(acc[rt][j], ah[rt], bh[j]);
                #pragma unroll
                for (int rt = 0; rt < 2; ++rt)
                    #pragma unroll
                    for (int j = 0; j < 4; ++j)
                        mma_bf16(acc[rt][j], ah[rt], bl[j]);
                #pragma unroll
                for (int rt = 0; rt < 2; ++rt)
                    #pragma unroll
                    for (int j = 0; j < 4; ++j)
                        mma_bf16(acc[rt][j], al[rt], bh[j]);
            }
        }

        // after kd0 compute: refill buf0 with slice kd2
        if (kd == 0) {
            __syncthreads();
            const long bo = (long)((b * 32 + d0 + 2) * 32 + hstart) * 1024;
            const uint32_t dh = smb + SLAB0;
            const uint32_t dl = dh + BUFSZ;
            for (int i = t; i < chunks; i += TPB) {
                cp_async16(dh + i * 16, (const char*)g_xt_hi + bo + (long)i * 16);
                cp_async16(dl + i * 16, (const char*)g_xt_lo + bo + (long)i * 16);
            }
            cp_commit();
        }
    }

    // ---- epilogue: stage accumulators to smem (pitch 33), then coalesced store
    __syncthreads();
    float* ep = (float*)sm;
    const int g  = lane >> 2;
    const int cq = 2 * (lane & 3);
    #pragma unroll
    for (int rt = 0; rt < 2; ++rt) {
        const int R = warp * 32 + rt * 16 + g;
        #pragma unroll
        for (int j = 0; j < 4; ++j) {
            const int col = j * 8 + cq;
            ep[R * 33 + col]           = acc[rt][j][0];
            ep[R * 33 + col + 1]       = acc[rt][j][1];
            ep[(R + 8) * 33 + col]     = acc[rt][j][2];
            ep[(R + 8) * 33 + col + 1] = acc[rt][j][3];
        }
    }
    __syncthreads();

    const int h = hstart + (t >> 5);
    const int w = t & 31;
    if (w < 30 && h < 30) {
        #pragma unroll 4
        for (int co = 0; co < 32; ++co) {
            const float v = ep[t * 33 + co];
            float y = fmaf(v, e1[co], e0[co]);
            y = tanhf(y) * e2s[co];
            out[((((long)b * 32 + co) * DO_ + d0) * 30 + h) * 30 + w] =
                1.0f / (1.0f + __expf(-y));
        }
    }
}

// ---------------- launch ----------------
extern "C" void kernel_launch(void* const* d_in, const int* in_sizes, int n_in,
                              void* d_out, int out_size)
{
    const float* x  = (const float*)d_in[0];
    const float* w  = (const float*)d_in[1];
    const float* cb = (const float*)d_in[2];
    const float* sf = (const float*)d_in[3];
    const float* bp = (const float*)d_in[4];
    float* out      = (float*)d_out;

    cudaFuncSetAttribute(conv_main, cudaFuncAttributeMaxDynamicSharedMemorySize, SMEM_DYN);

    xform_x<<<16 * 32 * 32, 128>>>(x);
    xform_w<<<(27 * 512 + 127) / 128, 128>>>(w);

    dim3 grid(DO_, 16, 4);
    conv_main<<<grid, TPB, SMEM_DYN>>>(cb, sf, bp, out);
}

// round 6
// speedup vs baseline: 2.9524x; 1.2789x over previous
#include <cuda_runtime.h>
#include <cuda_fp16.h>
#include <cstdint>
#include <math.h>

#define DO_   30
#define TPB   256

// ---------------- device scratch (no runtime alloc) ----------------
// x transformed to [b][d][h][w][cin] fp16, hi/lo split (x = hi + lo exactly to 2^-22)
__device__ __align__(16) __half g_xt_hi[16 * 32 * 32 * 32 * 16];
__device__ __align__(16) __half g_xt_lo[16 * 32 * 32 * 32 * 16];
// weights [tap 27][cout 32][cin 16] fp16 (single precision image)
__device__ __align__(16) __half g_w2[27 * 32 * 16];

// ---------------- helpers ----------------
__device__ __forceinline__ uint32_t smem_u32(const void* p) {
    uint32_t a;
    asm("{ .reg .u64 t; cvta.to.shared.u64 t, %1; cvt.u32.u64 %0, t; }" : "=r"(a) : "l"(p));
    return a;
}
__device__ __forceinline__ void cp_async16(uint32_t sdst, const void* gsrc) {
    asm volatile("cp.async.cg.shared.global [%0], [%1], 16;\n" :: "r"(sdst), "l"(gsrc));
}
__device__ __forceinline__ void cp_commit() { asm volatile("cp.async.commit_group;\n" ::: "memory"); }
template<int N> __device__ __forceinline__ void cp_wait() {
    asm volatile("cp.async.wait_group %0;\n" :: "n"(N) : "memory");
}
__device__ __forceinline__ void ldsm4(uint32_t* r, uint32_t addr) {
    asm volatile("ldmatrix.sync.aligned.m8n8.x4.shared.b16 {%0,%1,%2,%3}, [%4];"
        : "=r"(r[0]), "=r"(r[1]), "=r"(r[2]), "=r"(r[3]) : "r"(addr));
}
__device__ __forceinline__ void mma_f16(float* c, const uint32_t* a, const uint32_t* b) {
    asm volatile(
        "mma.sync.aligned.m16n8k16.row.col.f32.f16.f16.f32 "
        "{%0,%1,%2,%3}, {%4,%5,%6,%7}, {%8,%9}, {%0,%1,%2,%3};"
        : "+f"(c[0]), "+f"(c[1]), "+f"(c[2]), "+f"(c[3])
        : "r"(a[0]), "r"(a[1]), "r"(a[2]), "r"(a[3]), "r"(b[0]), "r"(b[1]));
}

// ---------------- transform kernels ----------------
// x: NCDHW fp32 -> g_xt_{hi,lo}[b][d][h][w][cin] fp16
__global__ __launch_bounds__(128) void xform_x(const float* __restrict__ x)
{
    __shared__ float s[16][33];
    const int blk = blockIdx.x;            // (b*32 + d)*32 + h
    const int b = blk >> 10, d = (blk >> 5) & 31, h = blk & 31;
    const int t = threadIdx.x;

    const int cin = t >> 3, w4 = (t & 7) << 2;
    const float4 v = *(const float4*)(x + (((long)(b * 16 + cin) << 15) + (d << 10) + (h << 5) + w4));
    s[cin][w4 + 0] = v.x; s[cin][w4 + 1] = v.y; s[cin][w4 + 2] = v.z; s[cin][w4 + 3] = v.w;
    __syncthreads();

    const long ob = (long)blk * 512;
    #pragma unroll
    for (int j = 0; j < 4; ++j) {
        const int e = t + (j << 7);        // = w*16 + cin
        const int w = e >> 4, c = e & 15;
        const float f = s[c][w];
        const __half hi = __float2half_rn(f);
        const __half lo = __float2half_rn(f - __half2float(hi));
        g_xt_hi[ob + e] = hi;
        g_xt_lo[ob + e] = lo;
    }
}

// weights OIDHW fp32 -> [tap][cout][cin] fp16
__global__ __launch_bounds__(128) void xform_w(const float* __restrict__ w)
{
    const int idx = blockIdx.x * 128 + threadIdx.x;
    if (idx >= 27 * 512) return;
    const int tap = idx >> 9, r = idx & 511;
    const int co = r >> 4, cin = r & 15;
    g_w2[tap * 512 + r] = __float2half_rn(w[(co * 16 + cin) * 27 + tap]);
}

// ---------------- main kernel ----------------
// dynamic smem (bytes):
//   [0, 27648)          weights [tap][32 co x 16 cin] (1024B per tap)
//   [27648, 68864)      slab: 4 buffers of 10304B = [buf(2)][prec(2)]
// epilogue overlays floats at offset 0: 256 x 33 x 4 = 33792B
#define SMEM_DYN 68864
#define SLAB0    27648
#define BUFSZ    10304

__global__ __launch_bounds__(TPB, 3) void conv_main(
    const float* __restrict__ cbias,
    const float* __restrict__ sfac,
    const float* __restrict__ bparm,
    float* __restrict__ out)
{
    extern __shared__ char sm[];
    __shared__ float e0[32], e1[32], e2s[32];

    const int d0 = blockIdx.x, b = blockIdx.y, hh = blockIdx.z;
    const int t = threadIdx.x, warp = t >> 5, lane = t & 31;
    const uint32_t smb = smem_u32(sm);
    const uint32_t ws_a = smb;

    const int hstart = hh * 8;
    const int rows_h = (hh == 3) ? 8 : 10;   // input h-rows (halo; clipped at bottom)
    const int chunks = rows_h * 64;          // 16B chunks per precision per slice

    // ---- async loads: G0 = weights + slice kd0 (buf0); G1 = slice kd1 (buf1)
    for (int i = t; i < 1728; i += TPB)
        cp_async16(ws_a + i * 16, (const char*)g_w2 + (long)i * 16);
    #pragma unroll
    for (int buf = 0; buf < 2; ++buf) {
        const long bo = (long)((b * 32 + d0 + buf) * 32 + hstart) * 1024;
        const uint32_t dh = smb + SLAB0 + (uint32_t)(buf * 2) * BUFSZ;
        const uint32_t dl = dh + BUFSZ;
        for (int i = t; i < chunks; i += TPB) {
            cp_async16(dh + i * 16, (const char*)g_xt_hi + bo + (long)i * 16);
            cp_async16(dl + i * 16, (const char*)g_xt_lo + bo + (long)i * 16);
        }
        cp_commit();
    }

    if (t < 32) {
        const float s = sfac[t];
        e0[t] = cbias[t] * s;
        e1[t] = s;
        e2s[t] = bparm[t];
    }

    float acc[2][4][4];
    #pragma unroll
    for (int rt = 0; rt < 2; ++rt)
        #pragma unroll
        for (int j = 0; j < 4; ++j)
            #pragma unroll
            for (int k = 0; k < 4; ++k)
                acc[rt][j][k] = 0.0f;

    const uint32_t bn = (lane & 7) + ((lane & 16) >> 1);
    const uint32_t bc = (lane & 8) * 2;
    const uint32_t ar = (lane & 15);
    const uint32_t ac = (lane & 16);

    #pragma unroll
    for (int kd = 0; kd < 3; ++kd) {
        if (kd < 2) cp_wait<1>(); else cp_wait<0>();
        __syncthreads();

        const uint32_t sh_a = smb + SLAB0 + (uint32_t)((kd & 1) * 2) * BUFSZ;
        const uint32_t sl_a = sh_a + BUFSZ;

        #pragma unroll
        for (int kh = 0; kh < 3; ++kh) {
            #pragma unroll
            for (int kw = 0; kw < 3; ++kw) {
                const int tap = (kd * 3 + kh) * 3 + kw;
                const uint32_t roff = (uint32_t)(kh * 32 + kw);

                // B fragments: 4 n8 coltiles (single precision image)
                uint32_t bh[4][2];
                {
                    const uint32_t base = ws_a + (uint32_t)tap * 1024u + bn * 32u + bc;
                    uint32_t r0[4], r1[4];
                    ldsm4(r0, base);            // n0-15
                    ldsm4(r1, base + 512u);     // n16-31
                    bh[0][0] = r0[0]; bh[0][1] = r0[1]; bh[1][0] = r0[2]; bh[1][1] = r0[3];
                    bh[2][0] = r1[0]; bh[2][1] = r1[1]; bh[3][0] = r1[2]; bh[3][1] = r1[3];
                }

                // A fragments for both rowtiles (hi and lo)
                uint32_t ah[2][4], al[2][4];
                const uint32_t arow0 = (uint32_t)(warp * 32) + roff + ar;
                #pragma unroll
                for (int rt = 0; rt < 2; ++rt) {
                    const uint32_t aoff = (arow0 + (uint32_t)rt * 16u) * 32u + ac;
                    ldsm4(ah[rt], sh_a + aoff);
                    ldsm4(al[rt], sl_a + aoff);
                }

                // Two passes; consecutive MMAs into same acc are 8 apart
                #pragma unroll
                for (int rt = 0; rt < 2; ++rt)
                    #pragma unroll
                    for (int j = 0; j < 4; ++j)
                        mma_f16(acc[rt][j], ah[rt], bh[j]);
                #pragma unroll
                for (int rt = 0; rt < 2; ++rt)
                    #pragma unroll
                    for (int j = 0; j < 4; ++j)
                        mma_f16(acc[rt][j], al[rt], bh[j]);
            }
        }

        // after kd0 compute: refill buf0 with slice kd2
        if (kd == 0) {
            __syncthreads();
            const long bo = (long)((b * 32 + d0 + 2) * 32 + hstart) * 1024;
            const uint32_t dh = smb + SLAB0;
            const uint32_t dl = dh + BUFSZ;
            for (int i = t; i < chunks; i += TPB) {
                cp_async16(dh + i * 16, (const char*)g_xt_hi + bo + (long)i * 16);
                cp_async16(dl + i * 16, (const char*)g_xt_lo + bo + (long)i * 16);
            }
            cp_commit();
        }
    }

    // ---- epilogue: stage accumulators to smem (pitch 33), then coalesced store
    __syncthreads();
    float* ep = (float*)sm;
    const int g  = lane >> 2;
    const int cq = 2 * (lane & 3);
    #pragma unroll
    for (int rt = 0; rt < 2; ++rt) {
        const int R = warp * 32 + rt * 16 + g;
        #pragma unroll
        for (int j = 0; j < 4; ++j) {
            const int col = j * 8 + cq;
            ep[R * 33 + col]           = acc[rt][j][0];
            ep[R * 33 + col + 1]       = acc[rt][j][1];
            ep[(R + 8) * 33 + col]     = acc[rt][j][2];
            ep[(R + 8) * 33 + col + 1] = acc[rt][j][3];
        }
    }
    __syncthreads();

    const int h = hstart + (t >> 5);
    const int w = t & 31;
    if (w < 30 && h < 30) {
        #pragma unroll 4
        for (int co = 0; co < 32; ++co) {
            const float v = ep[t * 33 + co];
            float y = fmaf(v, e1[co], e0[co]);
            y = tanhf(y) * e2s[co];
            out[((((long)b * 32 + co) * DO_ + d0) * 30 + h) * 30 + w] =
                1.0f / (1.0f + __expf(-y));
        }
    }
}

// ---------------- launch ----------------
extern "C" void kernel_launch(void* const* d_in, const int* in_sizes, int n_in,
                              void* d_out, int out_size)
{
    const float* x  = (const float*)d_in[0];
    const float* w  = (const float*)d_in[1];
    const float* cb = (const float*)d_in[2];
    const float* sf = (const float*)d_in[3];
    const float* bp = (const float*)d_in[4];
    float* out      = (float*)d_out;

    cudaFuncSetAttribute(conv_main, cudaFuncAttributeMaxDynamicSharedMemorySize, SMEM_DYN);

    xform_x<<<16 * 32 * 32, 128>>>(x);
    xform_w<<<(27 * 512 + 127) / 128, 128>>>(w);

    dim3 grid(DO_, 16, 4);
    conv_main<<<grid, TPB, SMEM_DYN>>>(cb, sf, bp, out);
}

// round 7
// speedup vs baseline: 3.7769x; 1.2793x over previous
#include <cuda_runtime.h>
#include <cuda_fp16.h>
#include <cstdint>
#include <math.h>

#define DO_   30
#define TPB   256

// ---------------- device scratch (no runtime alloc) ----------------
// x transformed to [b][d][h][w][cin] fp16
__device__ __align__(16) __half g_xt[16 * 32 * 32 * 32 * 16];
// weights [tap 27][cout 32][cin 16] fp16
__device__ __align__(16) __half g_w2[27 * 32 * 16];

// ---------------- helpers ----------------
__device__ __forceinline__ uint32_t smem_u32(const void* p) {
    uint32_t a;
    asm("{ .reg .u64 t; cvta.to.shared.u64 t, %1; cvt.u32.u64 %0, t; }" : "=r"(a) : "l"(p));
    return a;
}
__device__ __forceinline__ void cp_async16(uint32_t sdst, const void* gsrc) {
    asm volatile("cp.async.cg.shared.global [%0], [%1], 16;\n" :: "r"(sdst), "l"(gsrc));
}
__device__ __forceinline__ void cp_commit() { asm volatile("cp.async.commit_group;\n" ::: "memory"); }
template<int N> __device__ __forceinline__ void cp_wait() {
    asm volatile("cp.async.wait_group %0;\n" :: "n"(N) : "memory");
}
__device__ __forceinline__ void ldsm4(uint32_t* r, uint32_t addr) {
    asm volatile("ldmatrix.sync.aligned.m8n8.x4.shared.b16 {%0,%1,%2,%3}, [%4];"
        : "=r"(r[0]), "=r"(r[1]), "=r"(r[2]), "=r"(r[3]) : "r"(addr));
}
__device__ __forceinline__ void mma_f16(float* c, const uint32_t* a, const uint32_t* b) {
    asm volatile(
        "mma.sync.aligned.m16n8k16.row.col.f32.f16.f16.f32 "
        "{%0,%1,%2,%3}, {%4,%5,%6,%7}, {%8,%9}, {%0,%1,%2,%3};"
        : "+f"(c[0]), "+f"(c[1]), "+f"(c[2]), "+f"(c[3])
        : "r"(a[0]), "r"(a[1]), "r"(a[2]), "r"(a[3]), "r"(b[0]), "r"(b[1]));
}

// ---------------- transform kernels ----------------
// x: NCDHW fp32 -> g_xt[b][d][h][w][cin] fp16
__global__ __launch_bounds__(128) void xform_x(const float* __restrict__ x)
{
    __shared__ float s[16][33];
    const int blk = blockIdx.x;            // (b*32 + d)*32 + h
    const int b = blk >> 10, d = (blk >> 5) & 31, h = blk & 31;
    const int t = threadIdx.x;

    const int cin = t >> 3, w4 = (t & 7) << 2;
    const float4 v = *(const float4*)(x + (((long)(b * 16 + cin) << 15) + (d << 10) + (h << 5) + w4));
    s[cin][w4 + 0] = v.x; s[cin][w4 + 1] = v.y; s[cin][w4 + 2] = v.z; s[cin][w4 + 3] = v.w;
    __syncthreads();

    const long ob = (long)blk * 512;
    #pragma unroll
    for (int j = 0; j < 4; ++j) {
        const int e = t + (j << 7);        // = w*16 + cin
        const int w = e >> 4, c = e & 15;
        g_xt[ob + e] = __float2half_rn(s[c][w]);
    }
}

// weights OIDHW fp32 -> [tap][cout][cin] fp16
__global__ __launch_bounds__(128) void xform_w(const float* __restrict__ w)
{
    const int idx = blockIdx.x * 128 + threadIdx.x;
    if (idx >= 27 * 512) return;
    const int tap = idx >> 9, r = idx & 511;
    const int co = r >> 4, cin = r & 15;
    g_w2[tap * 512 + r] = __float2half_rn(w[(co * 16 + cin) * 27 + tap]);
}

// ---------------- main kernel ----------------
// dynamic smem (bytes):
//   [0, 27648)          weights [tap][32 co x 16 cin] (1024B per tap)
//   [27648, 48256)      slab: 2 buffers of 10304B
// epilogue overlays floats at offset 0: 256 x 33 x 4 = 33792B
#define SMEM_DYN 48256
#define SLAB0    27648
#define BUFSZ    10304

__global__ __launch_bounds__(TPB, 3) void conv_main(
    const float* __restrict__ cbias,
    const float* __restrict__ sfac,
    const float* __restrict__ bparm,
    float* __restrict__ out)
{
    extern __shared__ char sm[];
    __shared__ float e0[32], e1[32], e2s[32];

    const int d0 = blockIdx.x, b = blockIdx.y, hh = blockIdx.z;
    const int t = threadIdx.x, warp = t >> 5, lane = t & 31;
    const uint32_t smb = smem_u32(sm);
    const uint32_t ws_a = smb;

    const int hstart = hh * 8;
    const int rows_h = (hh == 3) ? 8 : 10;   // input h-rows (halo; clipped at bottom)
    const int chunks = rows_h * 64;          // 16B chunks per slice

    // ---- async loads: G0 = weights + slice kd0 (buf0); G1 = slice kd1 (buf1)
    for (int i = t; i < 1728; i += TPB)
        cp_async16(ws_a + i * 16, (const char*)g_w2 + (long)i * 16);
    #pragma unroll
    for (int buf = 0; buf < 2; ++buf) {
        const long bo = (long)((b * 32 + d0 + buf) * 32 + hstart) * 1024;
        const uint32_t dh = smb + SLAB0 + (uint32_t)buf * BUFSZ;
        for (int i = t; i < chunks; i += TPB)
            cp_async16(dh + i * 16, (const char*)g_xt + bo + (long)i * 16);
        cp_commit();
    }

    if (t < 32) {
        const float s = sfac[t];
        e0[t] = cbias[t] * s;
        e1[t] = s;
        e2s[t] = bparm[t];
    }

    float acc[2][4][4];
    #pragma unroll
    for (int rt = 0; rt < 2; ++rt)
        #pragma unroll
        for (int j = 0; j < 4; ++j)
            #pragma unroll
            for (int k = 0; k < 4; ++k)
                acc[rt][j][k] = 0.0f;

    const uint32_t bn = (lane & 7) + ((lane & 16) >> 1);
    const uint32_t bc = (lane & 8) * 2;
    const uint32_t ar = (lane & 15);
    const uint32_t ac = (lane & 16);

    #pragma unroll
    for (int kd = 0; kd < 3; ++kd) {
        if (kd < 2) cp_wait<1>(); else cp_wait<0>();
        __syncthreads();

        const uint32_t sh_a = smb + SLAB0 + (uint32_t)(kd & 1) * BUFSZ;

        #pragma unroll
        for (int kh = 0; kh < 3; ++kh) {
            #pragma unroll
            for (int kw = 0; kw < 3; ++kw) {
                const int tap = (kd * 3 + kh) * 3 + kw;
                const uint32_t roff = (uint32_t)(kh * 32 + kw);

                // B fragments: 4 n8 coltiles
                uint32_t bh[4][2];
                {
                    const uint32_t base = ws_a + (uint32_t)tap * 1024u + bn * 32u + bc;
                    uint32_t r0[4], r1[4];
                    ldsm4(r0, base);            // n0-15
                    ldsm4(r1, base + 512u);     // n16-31
                    bh[0][0] = r0[0]; bh[0][1] = r0[1]; bh[1][0] = r0[2]; bh[1][1] = r0[3];
                    bh[2][0] = r1[0]; bh[2][1] = r1[1]; bh[3][0] = r1[2]; bh[3][1] = r1[3];
                }

                // A fragments for both rowtiles
                uint32_t ah[2][4];
                const uint32_t arow0 = (uint32_t)(warp * 32) + roff + ar;
                #pragma unroll
                for (int rt = 0; rt < 2; ++rt) {
                    const uint32_t aoff = (arow0 + (uint32_t)rt * 16u) * 32u + ac;
                    ldsm4(ah[rt], sh_a + aoff);
                }

                #pragma unroll
                for (int rt = 0; rt < 2; ++rt)
                    #pragma unroll
                    for (int j = 0; j < 4; ++j)
                        mma_f16(acc[rt][j], ah[rt], bh[j]);
            }
        }

        // after kd0 compute: refill buf0 with slice kd2
        if (kd == 0) {
            __syncthreads();
            const long bo = (long)((b * 32 + d0 + 2) * 32 + hstart) * 1024;
            const uint32_t dh = smb + SLAB0;
            for (int i = t; i < chunks; i += TPB)
                cp_async16(dh + i * 16, (const char*)g_xt + bo + (long)i * 16);
            cp_commit();
        }
    }

    // ---- epilogue: stage accumulators to smem (pitch 33), then coalesced store
    __syncthreads();
    float* ep = (float*)sm;
    const int g  = lane >> 2;
    const int cq = 2 * (lane & 3);
    #pragma unroll
    for (int rt = 0; rt < 2; ++rt) {
        const int R = warp * 32 + rt * 16 + g;
        #pragma unroll
        for (int j = 0; j < 4; ++j) {
            const int col = j * 8 + cq;
            ep[R * 33 + col]           = acc[rt][j][0];
            ep[R * 33 + col + 1]       = acc[rt][j][1];
            ep[(R + 8) * 33 + col]     = acc[rt][j][2];
            ep[(R + 8) * 33 + col + 1] = acc[rt][j][3];
        }
    }
    __syncthreads();

    const int h = hstart + (t >> 5);
    const int w = t & 31;
    if (w < 30 && h < 30) {
        #pragma unroll 4
        for (int co = 0; co < 32; ++co) {
            const float v = ep[t * 33 + co];
            float y = fmaf(v, e1[co], e0[co]);
            y = tanhf(y) * e2s[co];
            out[((((long)b * 32 + co) * DO_ + d0) * 30 + h) * 30 + w] =
                1.0f / (1.0f + __expf(-y));
        }
    }
}

// ---------------- launch ----------------
extern "C" void kernel_launch(void* const* d_in, const int* in_sizes, int n_in,
                              void* d_out, int out_size)
{
    const float* x  = (const float*)d_in[0];
    const float* w  = (const float*)d_in[1];
    const float* cb = (const float*)d_in[2];
    const float* sf = (const float*)d_in[3];
    const float* bp = (const float*)d_in[4];
    float* out      = (float*)d_out;

    cudaFuncSetAttribute(conv_main, cudaFuncAttributeMaxDynamicSharedMemorySize, SMEM_DYN);

    xform_x<<<16 * 32 * 32, 128>>>(x);
    xform_w<<<(27 * 512 + 127) / 128, 128>>>(w);

    dim3 grid(DO_, 16, 4);
    conv_main<<<grid, TPB, SMEM_DYN>>>(cb, sf, bp, out);
}

// round 8
// speedup vs baseline: 4.3680x; 1.1565x over previous
#include <cuda_runtime.h>
#include <cuda_fp16.h>
#include <cstdint>
#include <math.h>

#define DO_   30
#define TPB   256

// ---------------- device scratch (no runtime alloc) ----------------
// x transformed to [b][d][h][w][cin] fp16
__device__ __align__(16) __half g_xt[16 * 32 * 32 * 32 * 16];
// weights [tap 27][cout 32][cin 16] fp16
__device__ __align__(16) __half g_w2[27 * 32 * 16];

// ---------------- helpers ----------------
__device__ __forceinline__ uint32_t smem_u32(const void* p) {
    uint32_t a;
    asm("{ .reg .u64 t; cvta.to.shared.u64 t, %1; cvt.u32.u64 %0, t; }" : "=r"(a) : "l"(p));
    return a;
}
__device__ __forceinline__ void cp_async16(uint32_t sdst, const void* gsrc) {
    asm volatile("cp.async.cg.shared.global [%0], [%1], 16;\n" :: "r"(sdst), "l"(gsrc));
}
__device__ __forceinline__ void cp_commit() { asm volatile("cp.async.commit_group;\n" ::: "memory"); }
template<int N> __device__ __forceinline__ void cp_wait() {
    asm volatile("cp.async.wait_group %0;\n" :: "n"(N) : "memory");
}
__device__ __forceinline__ void ldsm4(uint32_t* r, uint32_t addr) {
    asm volatile("ldmatrix.sync.aligned.m8n8.x4.shared.b16 {%0,%1,%2,%3}, [%4];"
        : "=r"(r[0]), "=r"(r[1]), "=r"(r[2]), "=r"(r[3]) : "r"(addr));
}
__device__ __forceinline__ void mma_f16(float* c, const uint32_t* a, const uint32_t* b) {
    asm volatile(
        "mma.sync.aligned.m16n8k16.row.col.f32.f16.f16.f32 "
        "{%0,%1,%2,%3}, {%4,%5,%6,%7}, {%8,%9}, {%0,%1,%2,%3};"
        : "+f"(c[0]), "+f"(c[1]), "+f"(c[2]), "+f"(c[3])
        : "r"(a[0]), "r"(a[1]), "r"(a[2]), "r"(a[3]), "r"(b[0]), "r"(b[1]));
}

// ---------------- merged transform kernel ----------------
// blocks [0, 16384): x NCDHW fp32 -> g_xt[b][d][h][w][cin] fp16
// blocks [16384, 16384+108): weights OIDHW fp32 -> g_w2[tap][cout][cin] fp16
__global__ __launch_bounds__(128) void xform_all(const float* __restrict__ x,
                                                 const float* __restrict__ w)
{
    const int t = threadIdx.x;
    if (blockIdx.x < 16384) {
        __shared__ float s[16][33];
        const int blk = blockIdx.x;            // (b*32 + d)*32 + h
        const int b = blk >> 10, d = (blk >> 5) & 31, h = blk & 31;

        const int cin = t >> 3, w4 = (t & 7) << 2;
        const float4 v = *(const float4*)(x + (((long)(b * 16 + cin) << 15) + (d << 10) + (h << 5) + w4));
        s[cin][w4 + 0] = v.x; s[cin][w4 + 1] = v.y; s[cin][w4 + 2] = v.z; s[cin][w4 + 3] = v.w;
        __syncthreads();

        const long ob = (long)blk * 512;
        #pragma unroll
        for (int j = 0; j < 4; ++j) {
            const int e = t + (j << 7);        // = w*16 + cin
            const int ww = e >> 4, c = e & 15;
            g_xt[ob + e] = __float2half_rn(s[c][ww]);
        }
    } else {
        const int idx = (blockIdx.x - 16384) * 128 + t;
        if (idx < 27 * 512) {
            const int tap = idx >> 9, r = idx & 511;
            const int co = r >> 4, cin = r & 15;
            g_w2[tap * 512 + r] = __float2half_rn(w[(co * 16 + cin) * 27 + tap]);
        }
    }
}

// ---------------- main kernel ----------------
// dynamic smem (bytes):
//   [0, 27648)          weights [tap][32 co x 16 cin] (1024B per tap)
//   [27648, 48256)      slab: 2 buffers of 10304B
// epilogue overlays floats at offset 0: 256 x 33 x 4 = 33792B
#define SMEM_DYN 48256
#define SLAB0    27648
#define BUFSZ    10304

__global__ __launch_bounds__(TPB, 3) void conv_main(
    const float* __restrict__ cbias,
    const float* __restrict__ sfac,
    const float* __restrict__ bparm,
    float* __restrict__ out)
{
    extern __shared__ char sm[];
    __shared__ float e0[32], e1[32], e2n[32];

    const int d0 = blockIdx.x, b = blockIdx.y, hh = blockIdx.z;
    const int t = threadIdx.x, warp = t >> 5, lane = t & 31;
    const uint32_t smb = smem_u32(sm);
    const uint32_t ws_a = smb;

    const int hstart = hh * 8;
    const int rows_h = (hh == 3) ? 8 : 10;   // input h-rows (halo; clipped at bottom)
    const int chunks = rows_h * 64;          // 16B chunks per slice

    // ---- async loads: G0 = weights + slice kd0 (buf0); G1 = slice kd1 (buf1)
    for (int i = t; i < 1728; i += TPB)
        cp_async16(ws_a + i * 16, (const char*)g_w2 + (long)i * 16);
    #pragma unroll
    for (int buf = 0; buf < 2; ++buf) {
        const long bo = (long)((b * 32 + d0 + buf) * 32 + hstart) * 1024;
        const uint32_t dh = smb + SLAB0 + (uint32_t)buf * BUFSZ;
        for (int i = t; i < chunks; i += TPB)
            cp_async16(dh + i * 16, (const char*)g_xt + bo + (long)i * 16);
        cp_commit();
    }

    if (t < 32) {
        const float s = sfac[t];
        e0[t] = cbias[t] * s;
        e1[t] = s;
        e2n[t] = -1.4426950408889634f * bparm[t];   // -log2(e) * bias_param
    }

    float acc[2][4][4];
    #pragma unroll
    for (int rt = 0; rt < 2; ++rt)
        #pragma unroll
        for (int j = 0; j < 4; ++j)
            #pragma unroll
            for (int k = 0; k < 4; ++k)
                acc[rt][j][k] = 0.0f;

    const uint32_t bn = (lane & 7) + ((lane & 16) >> 1);
    const uint32_t bc = (lane & 8) * 2;
    const uint32_t ar = (lane & 15);
    const uint32_t ac = (lane & 16);

    #pragma unroll
    for (int kd = 0; kd < 3; ++kd) {
        if (kd < 2) cp_wait<1>(); else cp_wait<0>();
        __syncthreads();

        const uint32_t sh_a = smb + SLAB0 + (uint32_t)(kd & 1) * BUFSZ;

        #pragma unroll
        for (int kh = 0; kh < 3; ++kh) {
            #pragma unroll
            for (int kw = 0; kw < 3; ++kw) {
                const int tap = (kd * 3 + kh) * 3 + kw;
                const uint32_t roff = (uint32_t)(kh * 32 + kw);

                // B fragments: 4 n8 coltiles
                uint32_t bh[4][2];
                {
                    const uint32_t base = ws_a + (uint32_t)tap * 1024u + bn * 32u + bc;
                    uint32_t r0[4], r1[4];
                    ldsm4(r0, base);            // n0-15
                    ldsm4(r1, base + 512u);     // n16-31
                    bh[0][0] = r0[0]; bh[0][1] = r0[1]; bh[1][0] = r0[2]; bh[1][1] = r0[3];
                    bh[2][0] = r1[0]; bh[2][1] = r1[1]; bh[3][0] = r1[2]; bh[3][1] = r1[3];
                }

                // A fragments for both rowtiles
                uint32_t ah[2][4];
                const uint32_t arow0 = (uint32_t)(warp * 32) + roff + ar;
                #pragma unroll
                for (int rt = 0; rt < 2; ++rt) {
                    const uint32_t aoff = (arow0 + (uint32_t)rt * 16u) * 32u + ac;
                    ldsm4(ah[rt], sh_a + aoff);
                }

                #pragma unroll
                for (int rt = 0; rt < 2; ++rt)
                    #pragma unroll
                    for (int j = 0; j < 4; ++j)
                        mma_f16(acc[rt][j], ah[rt], bh[j]);
            }
        }

        // after kd0 compute: refill buf0 with slice kd2
        if (kd == 0) {
            __syncthreads();
            const long bo = (long)((b * 32 + d0 + 2) * 32 + hstart) * 1024;
            const uint32_t dh = smb + SLAB0;
            for (int i = t; i < chunks; i += TPB)
                cp_async16(dh + i * 16, (const char*)g_xt + bo + (long)i * 16);
            cp_commit();
        }
    }

    // ---- epilogue: stage accumulators to smem (pitch 33), then coalesced store
    __syncthreads();
    float* ep = (float*)sm;
    const int g  = lane >> 2;
    const int cq = 2 * (lane & 3);
    #pragma unroll
    for (int rt = 0; rt < 2; ++rt) {
        const int R = warp * 32 + rt * 16 + g;
        #pragma unroll
        for (int j = 0; j < 4; ++j) {
            const int col = j * 8 + cq;
            ep[R * 33 + col]           = acc[rt][j][0];
            ep[R * 33 + col + 1]       = acc[rt][j][1];
            ep[(R + 8) * 33 + col]     = acc[rt][j][2];
            ep[(R + 8) * 33 + col + 1] = acc[rt][j][3];
        }
    }
    __syncthreads();

    const int h = hstart + (t >> 5);
    const int w = t & 31;
    if (w < 30 && h < 30) {
        float* ob = out + (((long)b * 32 * DO_ + d0) * 30 + h) * 30 + w;
        #pragma unroll 8
        for (int co = 0; co < 32; ++co) {
            const float v = ep[t * 33 + co];
            const float y = fmaf(v, e1[co], e0[co]);
            float th; asm("tanh.approx.f32 %0, %1;" : "=f"(th) : "f"(y));
            const float z = th * e2n[co];
            float ex; asm("ex2.approx.f32 %0, %1;" : "=f"(ex) : "f"(z));
            float sg; asm("rcp.approx.f32 %0, %1;" : "=f"(sg) : "f"(1.0f + ex));
            ob[(long)co * (DO_ * 30 * 30)] = sg;
        }
    }
}

// ---------------- launch ----------------
extern "C" void kernel_launch(void* const* d_in, const int* in_sizes, int n_in,
                              void* d_out, int out_size)
{
    const float* x  = (const float*)d_in[0];
    const float* w  = (const float*)d_in[1];
    const float* cb = (const float*)d_in[2];
    const float* sf = (const float*)d_in[3];
    const float* bp = (const float*)d_in[4];
    float* out      = (float*)d_out;

    cudaFuncSetAttribute(conv_main, cudaFuncAttributeMaxDynamicSharedMemorySize, SMEM_DYN);

    xform_all<<<16384 + 108, 128>>>(x, w);

    dim3 grid(DO_, 16, 4);
    conv_main<<<grid, TPB, SMEM_DYN>>>(cb, sf, bp, out);
}

// round 9
// speedup vs baseline: 5.3450x; 1.2237x over previous
#include <cuda_runtime.h>
#include <cuda_fp16.h>
#include <cstdint>
#include <math.h>

#define DO_   30
#define TPB   256

// ---------------- device scratch (no runtime alloc) ----------------
// x transformed to [b][d][h][w][cin] fp16
__device__ __align__(16) __half g_xt[16 * 32 * 32 * 32 * 16];
// weights [tap 27][cout 32][cin 16] fp16
__device__ __align__(16) __half g_w2[27 * 32 * 16];

// ---------------- helpers ----------------
__device__ __forceinline__ uint32_t smem_u32(const void* p) {
    uint32_t a;
    asm("{ .reg .u64 t; cvta.to.shared.u64 t, %1; cvt.u32.u64 %0, t; }" : "=r"(a) : "l"(p));
    return a;
}
__device__ __forceinline__ void cp_async16(uint32_t sdst, const void* gsrc) {
    asm volatile("cp.async.cg.shared.global [%0], [%1], 16;\n" :: "r"(sdst), "l"(gsrc));
}
__device__ __forceinline__ void cp_commit() { asm volatile("cp.async.commit_group;\n" ::: "memory"); }
template<int N> __device__ __forceinline__ void cp_wait() {
    asm volatile("cp.async.wait_group %0;\n" :: "n"(N) : "memory");
}
__device__ __forceinline__ void ldsm4(uint32_t* r, uint32_t addr) {
    asm volatile("ldmatrix.sync.aligned.m8n8.x4.shared.b16 {%0,%1,%2,%3}, [%4];"
        : "=r"(r[0]), "=r"(r[1]), "=r"(r[2]), "=r"(r[3]) : "r"(addr));
}
__device__ __forceinline__ void mma_f16(float* c, const uint32_t* a, const uint32_t* b) {
    asm volatile(
        "mma.sync.aligned.m16n8k16.row.col.f32.f16.f16.f32 "
        "{%0,%1,%2,%3}, {%4,%5,%6,%7}, {%8,%9}, {%0,%1,%2,%3};"
        : "+f"(c[0]), "+f"(c[1]), "+f"(c[2]), "+f"(c[3])
        : "r"(a[0]), "r"(a[1]), "r"(a[2]), "r"(a[3]), "r"(b[0]), "r"(b[1]));
}

// ---------------- merged transform kernel ----------------
__global__ __launch_bounds__(128) void xform_all(const float* __restrict__ x,
                                                 const float* __restrict__ w)
{
    const int t = threadIdx.x;
    if (blockIdx.x < 16384) {
        __shared__ float s[16][33];
        const int blk = blockIdx.x;            // (b*32 + d)*32 + h
        const int b = blk >> 10, d = (blk >> 5) & 31, h = blk & 31;

        const int cin = t >> 3, w4 = (t & 7) << 2;
        const float4 v = *(const float4*)(x + (((long)(b * 16 + cin) << 15) + (d << 10) + (h << 5) + w4));
        s[cin][w4 + 0] = v.x; s[cin][w4 + 1] = v.y; s[cin][w4 + 2] = v.z; s[cin][w4 + 3] = v.w;
        __syncthreads();

        const long ob = (long)blk * 512;
        #pragma unroll
        for (int j = 0; j < 4; ++j) {
            const int e = t + (j << 7);        // = w*16 + cin
            const int ww = e >> 4, c = e & 15;
            g_xt[ob + e] = __float2half_rn(s[c][ww]);
        }
    } else {
        const int idx = (blockIdx.x - 16384) * 128 + t;
        if (idx < 27 * 512) {
            const int tap = idx >> 9, r = idx & 511;
            const int co = r >> 4, cin = r & 15;
            g_w2[tap * 512 + r] = __float2half_rn(w[(co * 16 + cin) * 27 + tap]);
        }
    }
}

// ---------------- main kernel ----------------
// M = 512 rows (16 h x 32 w) per CTA; 8 warps x 4 rowtiles.
// dynamic smem (bytes):
//   [0, 27648)          weights [tap][32 co x 16 cin] (1024B per tap)
//   [27648, 64640)      slab: 2 buffers of 18496B (578 rows x 32B; 18 h-rows + 2 pad)
// epilogue overlays floats at offset 0: 512 x 33 x 4 = 67584B
#define SMEM_DYN 67584
#define SLAB0    27648
#define BUFSZ    18496

__global__ __launch_bounds__(TPB, 2) void conv_main(
    const float* __restrict__ cbias,
    const float* __restrict__ sfac,
    const float* __restrict__ bparm,
    float* __restrict__ out)
{
    extern __shared__ char sm[];
    __shared__ float e0[32], e1[32], e2n[32];

    const int d0 = blockIdx.x, b = blockIdx.y, hh = blockIdx.z;
    const int t = threadIdx.x, warp = t >> 5, lane = t & 31;
    const uint32_t smb = smem_u32(sm);
    const uint32_t ws_a = smb;

    const int hstart = hh * 16;
    const int rows_h = hh ? 16 : 18;         // input h-rows (halo below; clipped at bottom half)
    const int chunks = rows_h * 64;          // 16B chunks per slice

    // ---- async loads: G0 = weights + slice kd0 (buf0); G1 = slice kd1 (buf1)
    for (int i = t; i < 1728; i += TPB)
        cp_async16(ws_a + i * 16, (const char*)g_w2 + (long)i * 16);
    #pragma unroll
    for (int buf = 0; buf < 2; ++buf) {
        const long bo = (long)((b * 32 + d0 + buf) * 32 + hstart) * 1024;
        const uint32_t dh = smb + SLAB0 + (uint32_t)buf * BUFSZ;
        for (int i = t; i < chunks; i += TPB)
            cp_async16(dh + i * 16, (const char*)g_xt + bo + (long)i * 16);
        cp_commit();
    }

    if (t < 32) {
        const float s = sfac[t];
        e0[t] = cbias[t] * s;
        e1[t] = s;
        e2n[t] = -1.4426950408889634f * bparm[t];   // -log2(e) * bias_param
    }

    float acc[4][4][4];
    #pragma unroll
    for (int rt = 0; rt < 4; ++rt)
        #pragma unroll
        for (int j = 0; j < 4; ++j)
            #pragma unroll
            for (int k = 0; k < 4; ++k)
                acc[rt][j][k] = 0.0f;

    const uint32_t bn = (lane & 7) + ((lane & 16) >> 1);
    const uint32_t bc = (lane & 8) * 2;
    const uint32_t ar = (lane & 15);
    const uint32_t ac = (lane & 16);

    #pragma unroll
    for (int kd = 0; kd < 3; ++kd) {
        if (kd < 2) cp_wait<1>(); else cp_wait<0>();
        __syncthreads();

        const uint32_t sh_a = smb + SLAB0 + (uint32_t)(kd & 1) * BUFSZ;

        #pragma unroll
        for (int kh = 0; kh < 3; ++kh) {
            #pragma unroll
            for (int kw = 0; kw < 3; ++kw) {
                const int tap = (kd * 3 + kh) * 3 + kw;
                const uint32_t roff = (uint32_t)(kh * 32 + kw);

                // B fragments: 4 n8 coltiles (shared image, all warps)
                uint32_t bh[4][2];
                {
                    const uint32_t base = ws_a + (uint32_t)tap * 1024u + bn * 32u + bc;
                    uint32_t r0[4], r1[4];
                    ldsm4(r0, base);            // n0-15
                    ldsm4(r1, base + 512u);     // n16-31
                    bh[0][0] = r0[0]; bh[0][1] = r0[1]; bh[1][0] = r0[2]; bh[1][1] = r0[3];
                    bh[2][0] = r1[0]; bh[2][1] = r1[1]; bh[3][0] = r1[2]; bh[3][1] = r1[3];
                }

                // A fragments: 4 rowtiles (M=64 per warp)
                uint32_t ah[4][4];
                const uint32_t arow0 = (uint32_t)(warp * 64) + roff + ar;
                #pragma unroll
                for (int rt = 0; rt < 4; ++rt) {
                    const uint32_t aoff = (arow0 + (uint32_t)rt * 16u) * 32u + ac;
                    ldsm4(ah[rt], sh_a + aoff);
                }

                #pragma unroll
                for (int rt = 0; rt < 4; ++rt)
                    #pragma unroll
                    for (int j = 0; j < 4; ++j)
                        mma_f16(acc[rt][j], ah[rt], bh[j]);
            }
        }

        // after kd0 compute: refill buf0 with slice kd2
        if (kd == 0) {
            __syncthreads();
            const long bo = (long)((b * 32 + d0 + 2) * 32 + hstart) * 1024;
            const uint32_t dh = smb + SLAB0;
            for (int i = t; i < chunks; i += TPB)
                cp_async16(dh + i * 16, (const char*)g_xt + bo + (long)i * 16);
            cp_commit();
        }
    }

    // ---- epilogue: stage accumulators to smem (pitch 33), then coalesced store
    __syncthreads();
    float* ep = (float*)sm;
    const int g  = lane >> 2;
    const int cq = 2 * (lane & 3);
    #pragma unroll
    for (int rt = 0; rt < 4; ++rt) {
        const int R = warp * 64 + rt * 16 + g;
        #pragma unroll
        for (int j = 0; j < 4; ++j) {
            const int col = j * 8 + cq;
            ep[R * 33 + col]           = acc[rt][j][0];
            ep[R * 33 + col + 1]       = acc[rt][j][1];
            ep[(R + 8) * 33 + col]     = acc[rt][j][2];
            ep[(R + 8) * 33 + col + 1] = acc[rt][j][3];
        }
    }
    __syncthreads();

    #pragma unroll
    for (int half = 0; half < 2; ++half) {
        const int r = half * 256 + t;            // 0..511
        const int h = hstart + (r >> 5);
        const int w = r & 31;
        if (w < 30 && h < 30) {
            float* ob = out + (((long)b * 32 * DO_ + d0) * 30 + h) * 30 + w;
            #pragma unroll 8
            for (int co = 0; co < 32; ++co) {
                const float v = ep[r * 33 + co];
                const float y = fmaf(v, e1[co], e0[co]);
                float th; asm("tanh.approx.f32 %0, %1;" : "=f"(th) : "f"(y));
                const float z = th * e2n[co];
                float ex; asm("ex2.approx.f32 %0, %1;" : "=f"(ex) : "f"(z));
                float sg; asm("rcp.approx.f32 %0, %1;" : "=f"(sg) : "f"(1.0f + ex));
                ob[(long)co * (DO_ * 30 * 30)] = sg;
            }
        }
    }
}

// ---------------- launch ----------------
extern "C" void kernel_launch(void* const* d_in, const int* in_sizes, int n_in,
                              void* d_out, int out_size)
{
    const float* x  = (const float*)d_in[0];
    const float* w  = (const float*)d_in[1];
    const float* cb = (const float*)d_in[2];
    const float* sf = (const float*)d_in[3];
    const float* bp = (const float*)d_in[4];
    float* out      = (float*)d_out;

    cudaFuncSetAttribute(conv_main, cudaFuncAttributeMaxDynamicSharedMemorySize, SMEM_DYN);

    xform_all<<<16384 + 108, 128>>>(x, w);

    dim3 grid(DO_, 16, 2);
    conv_main<<<grid, TPB, SMEM_DYN>>>(cb, sf, bp, out);
}